// round 1
// baseline (speedup 1.0000x reference)
#include <cuda_runtime.h>

constexpr int B = 4, N = 512, HID = 256, H = 8, E = 32, DK = 32;
constexpr float SCALE = 0.17677669529663687f;   // 32^-0.5
constexpr float NEGV  = -9.0e15f;

// ---------------- scratch (static device globals; no runtime allocation) ----
__device__ float gQh [B*N*HID];
__device__ float gKh [B*N*HID];
__device__ float gVh [B*N*HID];
__device__ float gX  [B*H*(size_t)N*N];   // x[b,h,i,j] post-mask
__device__ float gEB [B*(size_t)N*N*H];   // edge_bias2[b,i,j,h] = proj[b,j,i,h]
__device__ float gWt [B*H*(size_t)N*N];   // combined softmax weights [b,h,i,j]
__device__ float gAtt[B*N*HID];           // (x_local+x_long) flattened [b,i,h*32+d]

// ============ GEMM: C[2048,256] = A[2048,256] @ W[256,256]^T + bias =========
__global__ __launch_bounds__(256) void gemm_nt_kernel(
    const float* __restrict__ A, const float* __restrict__ W,
    const float* __restrict__ bias, float* __restrict__ C)
{
    constexpr int Kd = 256;
    __shared__ float As[16][68];
    __shared__ float Bs[16][68];
    const int l  = threadIdx.x;
    const int tx = l & 15, ty = l >> 4;
    const int m0 = blockIdx.y * 64, n0 = blockIdx.x * 64;
    const int lrow = l >> 2, lq = l & 3;
    float acc[4][4] = {};
    for (int k0 = 0; k0 < Kd; k0 += 16) {
        float4 a4 = *(const float4*)(A + (size_t)(m0 + lrow) * Kd + k0 + lq * 4);
        float4 b4 = *(const float4*)(W + (size_t)(n0 + lrow) * Kd + k0 + lq * 4);
        As[lq*4+0][lrow] = a4.x; As[lq*4+1][lrow] = a4.y;
        As[lq*4+2][lrow] = a4.z; As[lq*4+3][lrow] = a4.w;
        Bs[lq*4+0][lrow] = b4.x; Bs[lq*4+1][lrow] = b4.y;
        Bs[lq*4+2][lrow] = b4.z; Bs[lq*4+3][lrow] = b4.w;
        __syncthreads();
        #pragma unroll
        for (int k = 0; k < 16; k++) {
            float4 av = *(const float4*)&As[k][ty*4];
            float4 bv = *(const float4*)&Bs[k][tx*4];
            float am[4] = {av.x, av.y, av.z, av.w};
            float bn[4] = {bv.x, bv.y, bv.z, bv.w};
            #pragma unroll
            for (int ii = 0; ii < 4; ii++)
                #pragma unroll
                for (int jj = 0; jj < 4; jj++)
                    acc[ii][jj] += am[ii] * bn[jj];
        }
        __syncthreads();
    }
    #pragma unroll
    for (int ii = 0; ii < 4; ii++) {
        int m = m0 + ty*4 + ii;
        float4 o;
        o.x = acc[ii][0] + bias[n0 + tx*4 + 0];
        o.y = acc[ii][1] + bias[n0 + tx*4 + 1];
        o.z = acc[ii][2] + bias[n0 + tx*4 + 2];
        o.w = acc[ii][3] + bias[n0 + tx*4 + 3];
        *(float4*)(C + (size_t)m * 256 + n0 + tx*4) = o;
    }
}

// ============ x[b,h,i,j] = mask(SCALE * Qh Kh^T)  (per (b,h) 512x512x32) ====
__global__ __launch_bounds__(256) void qk_kernel(const float* __restrict__ adj,
                                                 const int* __restrict__ use_adj)
{
    __shared__ float Qs[32][132];
    __shared__ float Ks[32][132];
    const int l  = threadIdx.x;
    const int bh = blockIdx.z, b = bh >> 3, h = bh & 7;
    const int i0 = blockIdx.y * 128, j0 = blockIdx.x * 128;
    const float* Qg = gQh + (size_t)b * N * HID + h * DK;
    const float* Kg = gKh + (size_t)b * N * HID + h * DK;
    #pragma unroll
    for (int it = 0; it < 4; it++) {
        int e = l + it * 256;
        int row = e >> 3, q4 = e & 7;
        float4 a4 = *(const float4*)(Qg + (size_t)(i0 + row) * HID + q4 * 4);
        float4 b4 = *(const float4*)(Kg + (size_t)(j0 + row) * HID + q4 * 4);
        Qs[q4*4+0][row] = a4.x; Qs[q4*4+1][row] = a4.y;
        Qs[q4*4+2][row] = a4.z; Qs[q4*4+3][row] = a4.w;
        Ks[q4*4+0][row] = b4.x; Ks[q4*4+1][row] = b4.y;
        Ks[q4*4+2][row] = b4.z; Ks[q4*4+3][row] = b4.w;
    }
    __syncthreads();
    const int tx = l & 15, ty = l >> 4;
    float acc[8][8] = {};
    #pragma unroll
    for (int k = 0; k < 32; k++) {
        float a[8], bb[8];
        float4 t0 = *(const float4*)&Qs[k][ty*8];
        float4 t1 = *(const float4*)&Qs[k][ty*8+4];
        a[0]=t0.x; a[1]=t0.y; a[2]=t0.z; a[3]=t0.w;
        a[4]=t1.x; a[5]=t1.y; a[6]=t1.z; a[7]=t1.w;
        float4 u0 = *(const float4*)&Ks[k][tx*8];
        float4 u1 = *(const float4*)&Ks[k][tx*8+4];
        bb[0]=u0.x; bb[1]=u0.y; bb[2]=u0.z; bb[3]=u0.w;
        bb[4]=u1.x; bb[5]=u1.y; bb[6]=u1.z; bb[7]=u1.w;
        #pragma unroll
        for (int ii = 0; ii < 8; ii++)
            #pragma unroll
            for (int jj = 0; jj < 8; jj++)
                acc[ii][jj] += a[ii] * bb[jj];
    }
    const int ua = use_adj[0];
    #pragma unroll
    for (int ii = 0; ii < 8; ii++) {
        int i = i0 + ty*8 + ii;
        const float* adjrow = adj + ((size_t)b * N + i) * N;
        float* xrow = gX + ((size_t)bh * N + i) * N;
        #pragma unroll
        for (int j4 = 0; j4 < 2; j4++) {
            int j = j0 + tx*8 + j4*4;
            float vv[4];
            #pragma unroll
            for (int jj = 0; jj < 4; jj++) {
                float v = acc[ii][j4*4+jj] * SCALE;
                if (ua) {
                    float a = adjrow[j + jj];
                    v = (a > 0.f ? v : NEGV) * a;
                }
                vv[jj] = v;
            }
            float4 o = {vv[0], vv[1], vv[2], vv[3]};
            *(float4*)(xrow + j) = o;
        }
    }
}

// ============ fused edge kernel: edge_out[b,p,q,:] and gEB[b,q,p,:] =========
__global__ __launch_bounds__(256) void edge_kernel(
    const float* __restrict__ edge_fea, const float* __restrict__ adj1,
    const float* __restrict__ Wap, const float* __restrict__ bap,
    const float* __restrict__ Wep, const float* __restrict__ bep,
    const float* __restrict__ Woe, float* __restrict__ edge_out)
{
    __shared__ float efs[16][513];                 // 16 p-rows x (16 q * 32 e)
    __shared__ float WapS[256], bapS[32], WepS[256], bepS[8], WoeS[1024];
    const int l = threadIdx.x;
    const int b = blockIdx.z;
    const int p0 = blockIdx.y * 16, q0 = blockIdx.x * 16;

    WapS[l] = Wap[l];
    WepS[l] = Wep[l];
    if (l < 32) bapS[l] = bap[l];
    if (l < 8)  bepS[l] = bep[l];
    for (int idx = l; idx < 1024; idx += 256) WoeS[idx] = Woe[idx];

    const int lr = l >> 4, lc = l & 15;
    const float* efbase = edge_fea + (((size_t)b * N + p0 + lr) * N + q0) * E;
    #pragma unroll
    for (int k = 0; k < 8; k++) {
        int c4 = lc + k * 16;
        float4 v = *(const float4*)(efbase + c4 * 4);
        efs[lr][c4*4+0] = v.x; efs[lr][c4*4+1] = v.y;
        efs[lr][c4*4+2] = v.z; efs[lr][c4*4+3] = v.w;
    }
    __syncthreads();

    const int tp = l & 15, tq = l >> 4;
    const int p = p0 + tp, q = q0 + tq;

    float eft[32];
    #pragma unroll
    for (int e = 0; e < 32; e++) eft[e] = efs[tp][tq*32 + e];
    float xh[8];
    #pragma unroll
    for (int hh = 0; hh < 8; hh++)
        xh[hh] = gX[(((size_t)b * H + hh) * N + q) * N + p];
    const float a1t = adj1[((size_t)b * N + q) * N + p];

    // edge_bias2[b, i=q, j=p, h] = edge_fea[b,p,q,:] . Wep[h,:] + bep[h]
    float* ebout = gEB + (((size_t)b * N + q) * N + p) * H;
    #pragma unroll
    for (int hh = 0; hh < 8; hh++) {
        float s = bepS[hh];
        #pragma unroll
        for (int e4 = 0; e4 < 8; e4++) {
            float4 w = *(const float4*)&WepS[hh*32 + e4*4];
            s += eft[e4*4+0]*w.x + eft[e4*4+1]*w.y + eft[e4*4+2]*w.z + eft[e4*4+3]*w.w;
        }
        ebout[hh] = s;
    }

    // t = ef + adj1[b,q,p] * (x[b,:,q,p] @ Wap^T + bap)
    #pragma unroll
    for (int e = 0; e < 32; e++) {
        float4 w0 = *(const float4*)&WapS[e*8];
        float4 w1 = *(const float4*)&WapS[e*8+4];
        float s = bapS[e]
                + xh[0]*w0.x + xh[1]*w0.y + xh[2]*w0.z + xh[3]*w0.w
                + xh[4]*w1.x + xh[5]*w1.y + xh[6]*w1.z + xh[7]*w1.w;
        eft[e] += a1t * s;
    }
    // eo = t @ Woe^T
    float eo[32];
    #pragma unroll
    for (int e2 = 0; e2 < 32; e2++) {
        float s = 0.f;
        #pragma unroll
        for (int e4 = 0; e4 < 8; e4++) {
            float4 w = *(const float4*)&WoeS[e2*32 + e4*4];
            s += eft[e4*4+0]*w.x + eft[e4*4+1]*w.y + eft[e4*4+2]*w.z + eft[e4*4+3]*w.w;
        }
        eo[e2] = s;
    }
    __syncthreads();
    #pragma unroll
    for (int e2 = 0; e2 < 32; e2++) efs[tp][tq*32 + e2] = eo[e2];
    __syncthreads();
    float* eob = edge_out + (((size_t)b * N + p0 + lr) * N + q0) * E;
    #pragma unroll
    for (int k = 0; k < 8; k++) {
        int c4 = lc + k * 16;
        float4 v = {efs[lr][c4*4+0], efs[lr][c4*4+1], efs[lr][c4*4+2], efs[lr][c4*4+3]};
        *(float4*)(eob + c4 * 4) = v;
    }
}

// ============ combined softmax weights: one block per (b,i), warp = head ====
__global__ __launch_bounds__(256) void softmax_kernel(
    const float* __restrict__ attn_bias, const float* __restrict__ adj1)
{
    const int bi = blockIdx.x;
    const int b = bi >> 9, i = bi & 511;
    const int h = threadIdx.x >> 5, lane = threadIdx.x & 31;
    const size_t bh = (size_t)b * H + h;
    const float* xrow  = gX + (bh * N + i) * N;
    const float* abrow = attn_bias + (bh * N + i) * N;
    const float* ebrow = gEB + (size_t)bi * N * H + h;
    const float* a1row = adj1 + (size_t)bi * N;

    float lgG[16], lgL[16];
    float mG = -3.4e38f, mL = -3.4e38f;
    #pragma unroll
    for (int k = 0; k < 16; k++) {
        int j = lane + k * 32;
        float xv = xrow[j];
        float g  = xv * abrow[j];
        float ll = xv * ebrow[(size_t)j * H] * a1row[j];
        lgG[k] = g; lgL[k] = ll;
        mG = fmaxf(mG, g); mL = fmaxf(mL, ll);
    }
    #pragma unroll
    for (int o = 16; o > 0; o >>= 1) {
        mG = fmaxf(mG, __shfl_xor_sync(0xffffffffu, mG, o));
        mL = fmaxf(mL, __shfl_xor_sync(0xffffffffu, mL, o));
    }
    float sG = 0.f, sL = 0.f;
    #pragma unroll
    for (int k = 0; k < 16; k++) {
        float eG = __expf(lgG[k] - mG);
        float eL = __expf(lgL[k] - mL);
        lgG[k] = eG; lgL[k] = eL;
        sG += eG; sL += eL;
    }
    #pragma unroll
    for (int o = 16; o > 0; o >>= 1) {
        sG += __shfl_xor_sync(0xffffffffu, sG, o);
        sL += __shfl_xor_sync(0xffffffffu, sL, o);
    }
    const float iG = 1.f / sG, iL = 1.f / sL;
    float* wrow = gWt + (bh * N + i) * N;
    #pragma unroll
    for (int k = 0; k < 16; k++)
        wrow[lane + k * 32] = lgG[k] * iG + lgL[k] * iL;
}

// ============ AV: gAtt[b,i,h*32+d] = sum_j gWt[b,h,i,j] * Vh[b,j,h*32+d] ====
__global__ __launch_bounds__(256) void av_kernel()
{
    __shared__ float Ws[32][132];
    __shared__ float Vs[32][36];
    const int l = threadIdx.x;
    const int bh = blockIdx.y, b = bh >> 3, h = bh & 7;
    const int i0 = blockIdx.x * 128;
    const float* Wg = gWt + ((size_t)bh * N + i0) * N;
    const float* Vg = gVh + (size_t)b * N * HID + h * DK;
    const int tx = l & 15, ty = l >> 4;
    float acc[8][2] = {};
    for (int k0 = 0; k0 < N; k0 += 32) {
        #pragma unroll
        for (int it = 0; it < 4; it++) {
            int e = l + it * 256;
            int row = e >> 3, q4 = e & 7;
            float4 v = *(const float4*)(Wg + (size_t)row * N + k0 + q4 * 4);
            Ws[q4*4+0][row] = v.x; Ws[q4*4+1][row] = v.y;
            Ws[q4*4+2][row] = v.z; Ws[q4*4+3][row] = v.w;
        }
        {
            int row = l >> 3, q4 = l & 7;
            float4 v = *(const float4*)(Vg + (size_t)(k0 + row) * HID + q4 * 4);
            *(float4*)&Vs[row][q4*4] = v;
        }
        __syncthreads();
        #pragma unroll
        for (int kk = 0; kk < 32; kk++) {
            float a[8];
            float4 t0 = *(const float4*)&Ws[kk][ty*8];
            float4 t1 = *(const float4*)&Ws[kk][ty*8+4];
            a[0]=t0.x; a[1]=t0.y; a[2]=t0.z; a[3]=t0.w;
            a[4]=t1.x; a[5]=t1.y; a[6]=t1.z; a[7]=t1.w;
            float2 bv = *(const float2*)&Vs[kk][tx*2];
            #pragma unroll
            for (int r = 0; r < 8; r++) {
                acc[r][0] += a[r] * bv.x;
                acc[r][1] += a[r] * bv.y;
            }
        }
        __syncthreads();
    }
    #pragma unroll
    for (int r = 0; r < 8; r++) {
        float2 o = {acc[r][0], acc[r][1]};
        *(float2*)(gAtt + ((size_t)b * N + i0 + ty*8 + r) * HID + h * DK + tx * 2) = o;
    }
}

// ===========================================================================
extern "C" void kernel_launch(void* const* d_in, const int* in_sizes, int n_in,
                              void* d_out, int out_size)
{
    (void)in_sizes; (void)n_in; (void)out_size;
    const float* q         = (const float*)d_in[0];
    const float* k         = (const float*)d_in[1];
    const float* v         = (const float*)d_in[2];
    const float* adj       = (const float*)d_in[3];
    const float* adj1      = (const float*)d_in[4];
    const float* edge_fea  = (const float*)d_in[5];
    const float* attn_bias = (const float*)d_in[6];
    const float* Wq = (const float*)d_in[7];
    const float* bq = (const float*)d_in[8];
    const float* Wk = (const float*)d_in[9];
    const float* bk = (const float*)d_in[10];
    const float* Wv = (const float*)d_in[11];
    const float* bv = (const float*)d_in[12];
    const float* Wap = (const float*)d_in[13];
    const float* bap = (const float*)d_in[14];
    const float* Wep = (const float*)d_in[15];
    const float* bep = (const float*)d_in[16];
    const float* Wo  = (const float*)d_in[17];
    const float* bo  = (const float*)d_in[18];
    const float* Woe = (const float*)d_in[19];
    const int* use_adj = (const int*)d_in[20];

    float* out      = (float*)d_out;
    float* edge_out = out + (size_t)B * N * HID;

    float *gq, *gk, *gv, *gatt;
    cudaGetSymbolAddress((void**)&gq, gQh);
    cudaGetSymbolAddress((void**)&gk, gKh);
    cudaGetSymbolAddress((void**)&gv, gVh);
    cudaGetSymbolAddress((void**)&gatt, gAtt);

    gemm_nt_kernel<<<dim3(4, 32), 256>>>(q, Wq, bq, gq);
    gemm_nt_kernel<<<dim3(4, 32), 256>>>(k, Wk, bk, gk);
    gemm_nt_kernel<<<dim3(4, 32), 256>>>(v, Wv, bv, gv);
    qk_kernel<<<dim3(4, 4, B * H), 256>>>(adj, use_adj);
    edge_kernel<<<dim3(N / 16, N / 16, B), 256>>>(edge_fea, adj1, Wap, bap,
                                                  Wep, bep, Woe, edge_out);
    softmax_kernel<<<B * N, 256>>>(attn_bias, adj1);
    av_kernel<<<dim3(N / 128, B * H), 256>>>();
    gemm_nt_kernel<<<dim3(4, 32), 256>>>(gatt, Wo, bo, out);
}